// round 15
// baseline (speedup 1.0000x reference)
#include <cuda_runtime.h>
#include <cstdint>

// TreeModel: depth-14 perfect binary heap, 32767 nodes, 16384 leaves, dim 512.
// out[0..16383] = dot(x[i], sum of deltas along root->leaf path)
// out[16384]    = sq[0] + sum_{n>=1} sq[n]/max(heights[n]-heights[parent],1e-7)
//
// R10 configuration + __launch_bounds__(256,7) on stream (force 7 CTAs/SM,
// regs <=36; R14 measured regs=38 -> 6 CTAs/SM, concurrency-limited BW).
// 2 kernels:
//  expand: 256 CTAs x 512 (CTA = level-8 subtree). 23 input rows loaded as
//          INDEPENDENT LDG.128s across 4 row-groups, staged in SMEM, combined
//          once -> 8 level-11 cum rows (g_cum). sq levels 0..11 folded at load
//          (owner-CTA gating) -> g_sqE[256].
//  stream: 2048 CTAs x 256 (tile = level-11 subtree, 8 leaves), 30KB smem:
//          mb0(TMA): cum row + lvl12 pair + lvl13 quad (14KB)
//          mb1(TMA): 8 leaf delta rows (16KB)
//          x read via 4 independent LDG.128 AFTER the mb1 wait.
//          (Verified regressions: L2 prefetch of x [R11], x-LDG hoist before
//           the wait [R12], per-slice leaf mbarriers [R13] -- all worse.)
//          sq levels 12..14 fused -> g_part[2048]; fence+counter last-CTA
//          reduces g_sqE+g_part in fixed order. Deterministic (no data atomics).

#define DIM 512
#define N_LEAVES 16384
#define NTILES 2048

__device__ __align__(128) float g_cum[NTILES * DIM];  // level-11 cums (4MB)
__device__ float g_sqE[256];
__device__ float g_part[NTILES];
__device__ unsigned int g_count = 0;

__device__ __forceinline__ float warp_sum(float v) {
#pragma unroll
    for (int o = 16; o > 0; o >>= 1) v += __shfl_down_sync(0xffffffffu, v, o);
    return v;
}
__device__ __forceinline__ float inv_branch(const float* __restrict__ h, int n) {
    return 1.0f / fmaxf(h[n] - h[(n - 1) >> 1], 1e-7f);
}
__device__ __forceinline__ float sq4(float4 v) {
    return fmaf(v.x, v.x, fmaf(v.y, v.y, fmaf(v.z, v.z, v.w * v.w)));
}
__device__ __forceinline__ float4 add4(float4 a, float4 b) {
    return make_float4(a.x + b.x, a.y + b.y, a.z + b.z, a.w + b.w);
}
__device__ __forceinline__ void bulk_cp(unsigned dst, const float* src, unsigned bytes, unsigned mb) {
    asm volatile("cp.async.bulk.shared::cta.global.mbarrier::complete_tx::bytes [%0], [%1], %2, [%3];"
                 :: "r"(dst), "l"(src), "r"(bytes), "r"(mb) : "memory");
}
__device__ __forceinline__ void mb_wait(unsigned mb) {
    asm volatile(
        "{\n\t.reg .pred p;\n\t"
        "W_%=:\n\t"
        "mbarrier.try_wait.parity.acquire.cta.shared::cta.b64 p, [%0], 0;\n\t"
        "@!p bra W_%=;\n\t}" :: "r"(mb) : "memory");
}

// ---------------- fused expand: levels 0..11, chainless ---------------------
// smem float4 rows: UP 3 @0, L9 2 @384, L10 4 @640, L11 8 @1152  (34KB)
__global__ __launch_bounds__(512) void expand_kernel(const float* __restrict__ deltas,
                                                     const float* __restrict__ heights) {
    __shared__ float4 sm[2176];
    __shared__ float red[16];

    const int r    = blockIdx.x;          // level-8 subtree 0..255
    const int tid  = threadIdx.x;
    const int q    = tid >> 7;            // row-group 0..3
    const int col  = tid & 127;           // float4 column
    const int w    = tid >> 5;
    const int lane = tid & 31;

    int anc[9];
    anc[8] = 255 + r;
#pragma unroll
    for (int l = 8; l > 0; --l) anc[l - 1] = (anc[l] - 1) >> 1;

    const int n9b  = 511 + 2 * r;
    const int n10b = 1023 + 4 * r;
    const int n11b = 2047 + 8 * r;

    float sqacc = 0.f;

    if (q < 3) {
        float4 u0 = ((const float4*)(deltas + (size_t)anc[3 * q + 0] * DIM))[col];
        float4 u1 = ((const float4*)(deltas + (size_t)anc[3 * q + 1] * DIM))[col];
        float4 u2 = ((const float4*)(deltas + (size_t)anc[3 * q + 2] * DIM))[col];
        int nm;
        if (q == 0) nm = n9b;
        else if (q == 1) nm = n9b + 1;
        else nm = n10b;
        float4 vm = ((const float4*)(deltas + (size_t)nm * DIM))[col];
        float4 va = ((const float4*)(deltas + (size_t)(n11b + 2 * q) * DIM))[col];
        float4 vb = ((const float4*)(deltas + (size_t)(n11b + 2 * q + 1) * DIM))[col];

#pragma unroll
        for (int k = 0; k < 3; ++k) {
            const int l = 3 * q + k;
            float4 u = (k == 0) ? u0 : (k == 1) ? u1 : u2;
            if ((r & ((1 << (8 - l)) - 1)) == 0) {
                float inv = (l == 0) ? 1.0f : inv_branch(heights, anc[l]);
                sqacc = fmaf(sq4(u), inv, sqacc);
            }
        }
        sqacc = fmaf(sq4(vm), inv_branch(heights, nm), sqacc);
        sqacc = fmaf(sq4(va), inv_branch(heights, n11b + 2 * q), sqacc);
        sqacc = fmaf(sq4(vb), inv_branch(heights, n11b + 2 * q + 1), sqacc);

        sm[q * 128 + col] = add4(add4(u0, u1), u2);
        if (q == 0)      sm[384 + col] = vm;
        else if (q == 1) sm[384 + 128 + col] = vm;
        else             sm[640 + col] = vm;
        sm[1152 + (2 * q) * 128 + col]     = va;
        sm[1152 + (2 * q + 1) * 128 + col] = vb;
    } else {
        float4 m1 = ((const float4*)(deltas + (size_t)(n10b + 1) * DIM))[col];
        float4 m2 = ((const float4*)(deltas + (size_t)(n10b + 2) * DIM))[col];
        float4 m3 = ((const float4*)(deltas + (size_t)(n10b + 3) * DIM))[col];
        float4 va = ((const float4*)(deltas + (size_t)(n11b + 6) * DIM))[col];
        float4 vb = ((const float4*)(deltas + (size_t)(n11b + 7) * DIM))[col];

        sqacc = fmaf(sq4(m1), inv_branch(heights, n10b + 1), sqacc);
        sqacc = fmaf(sq4(m2), inv_branch(heights, n10b + 2), sqacc);
        sqacc = fmaf(sq4(m3), inv_branch(heights, n10b + 3), sqacc);
        sqacc = fmaf(sq4(va), inv_branch(heights, n11b + 6), sqacc);
        sqacc = fmaf(sq4(vb), inv_branch(heights, n11b + 7), sqacc);

        sm[640 + 128 + col] = m1;
        sm[640 + 256 + col] = m2;
        sm[640 + 384 + col] = m3;
        sm[1152 + 6 * 128 + col] = va;
        sm[1152 + 7 * 128 + col] = vb;
    }
    __syncthreads();

    float4 up = add4(add4(sm[col], sm[128 + col]), sm[256 + col]);
#pragma unroll
    for (int k = 0; k < 2; ++k) {
        const int j = 2 * q + k;
        float4 v = add4(up, sm[384 + (j >> 2) * 128 + col]);
        v = add4(v, sm[640 + (j >> 1) * 128 + col]);
        v = add4(v, sm[1152 + j * 128 + col]);
        ((float4*)(g_cum + (size_t)(8 * r + j) * DIM))[col] = v;
    }

    sqacc = warp_sum(sqacc);
    if (lane == 0) red[w] = sqacc;
    __syncthreads();
    if (tid == 0) {
        float t = 0.f;
#pragma unroll
        for (int j = 0; j < 16; ++j) t += red[j];
        g_sqE[r] = t;
    }
}

// ---------------- stream: leaves + dots + final reduce ----------------------
// smem float4 offsets: CUM 0 (1 row), D12 128 (2), D13 384 (4), DL 896 (8)
__global__ __launch_bounds__(256, 7) void stream_kernel(const float* __restrict__ x,
                                                        const float* __restrict__ deltas,
                                                        const float* __restrict__ heights,
                                                        float* __restrict__ out) {
    __shared__ float4 sm[1920];       // 30 KB
    __shared__ float  redL[32];
    __shared__ float  redS[8];
    __shared__ int    is_last;
    __shared__ __align__(8) unsigned long long mbar[2];

    const int b    = blockIdx.x;      // tile = level-11 subtree
    const int tid  = threadIdx.x;
    const int col  = tid & 127;
    const int g    = tid >> 7;        // slice 0/1
    const int w    = tid >> 5;
    const int ws   = w & 3;
    const int lane = tid & 31;

    const unsigned mb0 = (unsigned)__cvta_generic_to_shared(&mbar[0]);
    const unsigned mb1 = (unsigned)__cvta_generic_to_shared(&mbar[1]);
    const unsigned smb = (unsigned)__cvta_generic_to_shared(sm);

    if (tid == 0) {
        asm volatile("mbarrier.init.shared.b64 [%0], %1;" :: "r"(mb0), "r"(1));
        asm volatile("mbarrier.init.shared.b64 [%0], %1;" :: "r"(mb1), "r"(1));
        asm volatile("fence.proxy.async.shared::cta;" ::: "memory");
        asm volatile("mbarrier.arrive.expect_tx.shared.b64 _, [%0], %1;" :: "r"(mb0), "r"(14336u));
        asm volatile("mbarrier.arrive.expect_tx.shared.b64 _, [%0], %1;" :: "r"(mb1), "r"(16384u));
        bulk_cp(smb + 0   * 16, g_cum + (size_t)b * DIM,                    2048u,  mb0);
        bulk_cp(smb + 128 * 16, deltas + (size_t)(4095 + 2 * b) * DIM,      4096u,  mb0);
        bulk_cp(smb + 384 * 16, deltas + (size_t)(8191 + 4 * b) * DIM,      8192u,  mb0);
        bulk_cp(smb + 896 * 16, deltas + (size_t)(N_LEAVES - 1 + 8 * b) * DIM, 16384u, mb1);
    }
    __syncthreads();

    // scalar inv factors (broadcast loads; overlap with TMA flight)
    const float inv12 = inv_branch(heights, 4095 + 2 * b + g);
    float inv13[2], inv14[4];
#pragma unroll
    for (int j = 0; j < 2; ++j) inv13[j] = inv_branch(heights, 8191 + 4 * b + 2 * g + j);
#pragma unroll
    for (int j = 0; j < 4; ++j) inv14[j] = inv_branch(heights, N_LEAVES - 1 + 8 * b + 4 * g + j);

    float sqacc = 0.f;

    // ---- weight path (mb0) --------------------------------------------------
    mb_wait(mb0);
    float4 c12;
    {
        float4 v = sm[128 + g * 128 + col];
        sqacc = fmaf(sq4(v), inv12, sqacc);
        c12 = add4(sm[col], v);
    }
    float4 c13[2];
#pragma unroll
    for (int j = 0; j < 2; ++j) {
        float4 v = sm[384 + (2 * g + j) * 128 + col];
        sqacc = fmaf(sq4(v), inv13[j], sqacc);
        c13[j] = add4(c12, v);
    }

    // ---- leaves (mb1) + x via independent LDG.128 after the wait ------------
    mb_wait(mb1);
    float4 xv[4];
#pragma unroll
    for (int j = 0; j < 4; ++j)       // 4 independent global loads, issued first
        xv[j] = ((const float4*)(x + (size_t)(8 * b + 4 * g + j) * DIM))[col];

    float acc[4];
#pragma unroll
    for (int j = 0; j < 4; ++j) {
        const int li = 4 * g + j;
        float4 dv = sm[896 + li * 128 + col];
        sqacc = fmaf(sq4(dv), inv14[j], sqacc);
        float4 wv = add4(c13[j >> 1], dv);
        float t;
        t = xv[j].x * wv.x;
        t = fmaf(xv[j].y, wv.y, t);
        t = fmaf(xv[j].z, wv.z, t);
        t = fmaf(xv[j].w, wv.w, t);
        acc[j] = warp_sum(t);
    }
    if (lane == 0) {
#pragma unroll
        for (int j = 0; j < 4; ++j) redL[(g * 4 + j) * 4 + ws] = acc[j];
    }

    sqacc = warp_sum(sqacc);
    if (lane == 0) redS[w] = sqacc;
    __syncthreads();

    if (tid < 8) {
        float r = redL[tid * 4] + redL[tid * 4 + 1] + redL[tid * 4 + 2] + redL[tid * 4 + 3];
        out[8 * b + tid] = r;
    }
    if (tid == 0) {
        float t = 0.f;
#pragma unroll
        for (int j = 0; j < 8; ++j) t += redS[j];
        g_part[b] = t;
        __threadfence();
        unsigned prev = atomicAdd(&g_count, 1u);
        is_last = (prev == NTILES - 1) ? 1 : 0;
    }
    __syncthreads();

    // ---- last CTA: deterministic final reduce (fixed order) -----------------
    if (is_last) {
        const volatile float* gE = g_sqE;
        const volatile float* gp = g_part;
        float s = (tid < 256) ? gE[tid] : 0.f;
#pragma unroll
        for (int r = 0; r < 8; ++r) s += gp[tid + 256 * r];
        s = warp_sum(s);
        if (lane == 0) redS[w] = s;
        __syncthreads();
        if (tid == 0) {
            float t = 0.f;
#pragma unroll
            for (int j = 0; j < 8; ++j) t += redS[j];
            out[N_LEAVES] = t;
            g_count = 0;              // reset for next graph replay
        }
    }
}

extern "C" void kernel_launch(void* const* d_in, const int* in_sizes, int n_in,
                              void* d_out, int out_size) {
    const float* x       = (const float*)d_in[0];
    const float* deltas  = (const float*)d_in[1];
    const float* heights = (const float*)d_in[2];
    float* out = (float*)d_out;

    expand_kernel<<<256, 512>>>(deltas, heights);
    stream_kernel<<<NTILES, 256>>>(x, deltas, heights, out);
}